// round 10
// baseline (speedup 1.0000x reference)
#include <cuda_runtime.h>
#include <math.h>

#define NB 32
#define NA 3
#define NH 52
#define NW 52
#define NG 50
#define NC 80
#define ATTRS 85
#define HW (NH * NW)              // 2704
#define F4C (HW / 4)              // 676
#define TPB 256
#define NCONF (NB * NA)           // 96 conf blocks: one full slice each
#define TGT_PER_WB 25
#define WB_PER_B 2
#define NWIN (NB * WB_PER_B)      // 64
#define GRID (NCONF + NWIN)       // 160
#define NITEMS_WB (TGT_PER_WB * ATTRS)  // 2125
#define IPT 9                     // ceil(2125/256)
#define CELLS (NB * NA * HW)      // 259584

// acc: 0=x 1=y 2=w 3=h 4=conf_obj 5=noobj 6=cls 7=npos (zero-init; last block resets)
__device__ float        g_acc[8];
__device__ unsigned int g_done;

__constant__ float c_aw[3] = {1.25f, 2.0f, 4.125f};
__constant__ float c_ah[3] = {1.625f, 3.75f, 2.875f};

__device__ __forceinline__ float sp(float x) {       // softplus
    return fmaxf(x, 0.0f) + __logf(1.0f + __expf(-fabsf(x)));
}
__device__ __forceinline__ float spu(float x) {      // 1 + e^-|x|
    return 1.0f + __expf(-fabsf(x));
}

__global__ void __launch_bounds__(TPB)
k_main(const float* __restrict__ in, const float* __restrict__ tg,
       float* __restrict__ out) {
    __shared__ float sacc[8];
    __shared__ unsigned int s_last;
    if (threadIdx.x < 8) sacc[threadIdx.x] = 0.0f;

    if (blockIdx.x < NCONF) {
        // ============ CONF / NOOBJ BLOCK: one full (b,a) slice ============
        const int b = blockIdx.x / NA;
        const int a = blockIdx.x % NA;

        __shared__ unsigned char ssup[HW];
        for (int i = threadIdx.x; i < HW; i += TPB) ssup[i] = 0;
        __syncthreads();

        if (threadIdx.x < NG) {
            const float* t = tg + (size_t)(b * NG + threadIdx.x) * 5;
            float gx = t[1] * ((float)NW / 416.0f);
            float gy = t[2] * ((float)NH / 416.0f);
            float gw = t[3] * ((float)NW / 416.0f);
            float gh = t[4] * ((float)NH / 416.0f);
            int gi = min(max((int)gx, 0), NW - 1);
            int gj = min(max((int)gy, 0), NH - 1);
            float area_g = (gw + 1.0f) * (gh + 1.0f);
            float iw = fmaxf(fminf(gw, c_aw[a]) + 1.0f, 0.0f);
            float ih = fmaxf(fminf(gh, c_ah[a]) + 1.0f, 0.0f);
            float inter = iw * ih;
            float area_a = (c_aw[a] + 1.0f) * (c_ah[a] + 1.0f);
            float iou = inter / (area_g + area_a - inter + 1e-16f);
            if (iou > 0.5f) ssup[gj * NW + gi] = 1;
        }
        __syncthreads();

        // noobj: 3 front-batched float4 loads per thread; one log per float4
        float snoobj = 0.f;
        const float4* confc =
            reinterpret_cast<const float4*>(in + (size_t)(b * 255 + a * ATTRS + 4) * HW);
        float4 cv[3];
        int fi[3];
#pragma unroll
        for (int i = 0; i < 3; i++) {
            int f = threadIdx.x + i * TPB;
            fi[i] = (f < F4C) ? f : -1;
            cv[i] = (f < F4C) ? confc[f]
                              : make_float4(0.f, 0.f, 0.f, 0.f);
        }
#pragma unroll
        for (int i = 0; i < 3; i++) {
            if (fi[i] < 0) continue;
            const int lb = fi[i] * 4;
            float lin = 0.0f, prod = 1.0f;
            if (!ssup[lb + 0]) { lin += fmaxf(cv[i].x, 0.0f); prod *= spu(cv[i].x); }
            if (!ssup[lb + 1]) { lin += fmaxf(cv[i].y, 0.0f); prod *= spu(cv[i].y); }
            if (!ssup[lb + 2]) { lin += fmaxf(cv[i].z, 0.0f); prod *= spu(cv[i].z); }
            if (!ssup[lb + 3]) { lin += fmaxf(cv[i].w, 0.0f); prod *= spu(cv[i].w); }
            snoobj += lin + __logf(prod);
        }
        unsigned lane = threadIdx.x & 31;
#pragma unroll
        for (int o = 16; o > 0; o >>= 1) snoobj += __shfl_down_sync(0xffffffffu, snoobj, o);
        if (lane == 0 && snoobj != 0.0f) atomicAdd(&sacc[5], snoobj);
    } else {
        // ============ WINNER BLOCK: 25 targets, 9 front-batched gathers/thread =====
        const int wb  = blockIdx.x - NCONF;
        const int b   = wb / WB_PER_B;
        const int lo  = (wb % WB_PER_B) * TGT_PER_WB;

        __shared__ int    s_base[NG];
        __shared__ float4 s_box[NG];       // tx, ty, tw, th
        __shared__ int    s_cls[NG];
        __shared__ int    s_key[NG];
        __shared__ unsigned char s_alive[NG];

        if (threadIdx.x < NG) {
            const int t_i = threadIdx.x;
            const float* t = tg + (size_t)(b * NG + t_i) * 5;
            float gx = t[1] * ((float)NW / 416.0f);
            float gy = t[2] * ((float)NH / 416.0f);
            float gw = t[3] * ((float)NW / 416.0f);
            float gh = t[4] * ((float)NH / 416.0f);
            int gi = min(max((int)gx, 0), NW - 1);
            int gj = min(max((int)gy, 0), NH - 1);
            int cell = gj * NW + gi;
            float area_g = (gw + 1.0f) * (gh + 1.0f);
            float best_iou = -1.0f;
            int best = 0;
#pragma unroll
            for (int k = 0; k < 3; k++) {
                float iw = fmaxf(fminf(gw, c_aw[k]) + 1.0f, 0.0f);
                float ih = fmaxf(fminf(gh, c_ah[k]) + 1.0f, 0.0f);
                float inter = iw * ih;
                float area_k = (c_aw[k] + 1.0f) * (c_ah[k] + 1.0f);
                float iou = inter / (area_g + area_k - inter + 1e-16f);
                if (iou > best_iou) { best_iou = iou; best = k; }  // first-max = jnp.argmax
            }
            s_key[t_i]  = best * HW + cell;
            s_base[t_i] = (b * 255 + best * ATTRS) * HW + cell;
            s_box[t_i]  = make_float4(gx - (float)gi, gy - (float)gj,
                                      logf(gw / c_aw[best] + 1e-16f),
                                      logf(gh / c_ah[best] + 1e-16f));
            s_cls[t_i]  = min(max((int)t[0], 0), NC - 1);
        }
        __syncthreads();
        if (threadIdx.x < NG) {
            unsigned char alive = 1;
            int key = s_key[threadIdx.x];
            for (int t2 = threadIdx.x + 1; t2 < NG; t2++)
                if (s_key[t2] == key) alive = 0;   // later scatter overwrites = max-g
            s_alive[threadIdx.x] = alive;
        }
        __syncthreads();

        float xv[IPT];
        int   tgi[IPT], chi[IPT];
#pragma unroll
        for (int i = 0; i < IPT; i++) {
            const int w = threadIdx.x + i * TPB;
            const bool valid = w < NITEMS_WB;
            const int tgt = lo + (valid ? w / ATTRS : 0);
            const int ch  = valid ? w % ATTRS : 0;
            const bool live = valid && s_alive[tgt];
            tgi[i] = live ? tgt : -1;
            chi[i] = ch;
            xv[i] = live ? __ldg(in + (size_t)s_base[tgt] + (size_t)ch * HW) : 0.0f;
        }
        // bce(sigm(x), t) = sp(x) - t*x; cls logs merged into one product per thread
        float ax = 0.f, ay = 0.f, aw2 = 0.f, ah2 = 0.f, ac = 0.f;
        float acls = 0.f, np = 0.f;
        float prodc = 1.0f;
#pragma unroll
        for (int i = 0; i < IPT; i++) {
            const int tgt = tgi[i];
            if (tgt < 0) continue;
            const float x = xv[i];
            const int ch = chi[i];
            if (ch >= 5) {
                float t = (ch - 5 == s_cls[tgt]) ? 1.0f : 0.0f;
                acls += fmaxf(x, 0.0f) - t * x;
                prodc *= spu(x);
                if (prodc > 1e30f) { acls += __logf(prodc); prodc = 1.0f; }
            } else if (ch == 0) {
                ax += sp(x) - s_box[tgt].x * x;
                np += 1.0f;
            } else if (ch == 1) {
                ay += sp(x) - s_box[tgt].y * x;
            } else if (ch == 2) {
                float d = x - s_box[tgt].z; aw2 += d * d;
            } else if (ch == 3) {
                float d = x - s_box[tgt].w; ah2 += d * d;
            } else {
                ac += sp(x) - x;                    // bce(conf, 1) = sp(-x)
            }
        }
        acls += __logf(prodc);

        float vals[7] = {ax, ay, aw2, ah2, ac, acls, np};
        const int map[7] = {0, 1, 2, 3, 4, 6, 7};
        unsigned lane = threadIdx.x & 31;
#pragma unroll
        for (int k = 0; k < 7; k++) {
            float v = vals[k];
#pragma unroll
            for (int o = 16; o > 0; o >>= 1) v += __shfl_down_sync(0xffffffffu, v, o);
            if (lane == 0 && v != 0.0f) atomicAdd(&sacc[map[k]], v);
        }
    }
    __syncthreads();

    // ---- 8 global float REDs per block, done-ticket, last block finalizes ----
    if (threadIdx.x < 8) {
        float v = sacc[threadIdx.x];
        if (v != 0.0f) atomicAdd(&g_acc[threadIdx.x], v);
    }
    if (threadIdx.x == 0) {
        __threadfence();
        unsigned int v = atomicAdd(&g_done, 1u);
        s_last = (v == (unsigned int)(GRID - 1)) ? 1u : 0u;
    }
    __syncthreads();
    if (s_last && threadIdx.x == 0) {
        const double N = (double)CELLS;
        double lx = (double)g_acc[0] / N;
        double ly = (double)g_acc[1] / N;
        double lw = (double)g_acc[2] / N;
        double lh = (double)g_acc[3] / N;
        double lconf = (double)g_acc[4] / N + 0.5 * ((double)g_acc[5] / N);
        double denom = (double)g_acc[7] * (double)NC;
        if (denom < 1.0) denom = 1.0;
        double lcls = (double)g_acc[6] / denom;
        out[0] = (float)(2.5 * (lx + ly) + 2.5 * (lw + lh) + lconf + lcls);
#pragma unroll
        for (int k = 0; k < 8; k++) g_acc[k] = 0.0f;   // restore pristine state
        g_done = 0u;
        __threadfence();
    }
}

extern "C" void kernel_launch(void* const* d_in, const int* in_sizes, int n_in,
                              void* d_out, int out_size) {
    const float* inp = (const float*)d_in[0];   // [32,255,52,52]
    const float* tgt = (const float*)d_in[1];   // [32,50,5]
    k_main<<<GRID, TPB>>>(inp, tgt, (float*)d_out);
}

// round 11
// speedup vs baseline: 1.3375x; 1.3375x over previous
#include <cuda_runtime.h>
#include <math.h>

#define NB 32
#define NA 3
#define NH 52
#define NW 52
#define NG 50
#define NC 80
#define ATTRS 85
#define HW (NH * NW)              // 2704
#define F4C (HW / 4)              // 676
#define TPB 256
#define BPS 3
#define CPB 1024
#define NCONF (NB * NA * BPS)     // 288
#define TGT_PER_WB 3              // 3*85 = 255 <= 256: ONE gather load per thread
#define WB_PER_B 17               // ceil(50/3)
#define NWIN (NB * WB_PER_B)      // 544
#define GRID (NCONF + NWIN)       // 832
#define CELLS (NB * NA * HW)      // 259584

// acc: 0=x 1=y 2=w 3=h 4=conf_obj 5=noobj 6=cls 7=npos (zero-init; last block resets)
__device__ float        g_acc[8];
__device__ unsigned int g_done;

__constant__ float c_aw[3] = {1.25f, 2.0f, 4.125f};
__constant__ float c_ah[3] = {1.625f, 3.75f, 2.875f};

__device__ __forceinline__ float sp(float x) {       // softplus
    return fmaxf(x, 0.0f) + __logf(1.0f + __expf(-fabsf(x)));
}
__device__ __forceinline__ float spu(float x) {      // 1 + e^-|x|
    return 1.0f + __expf(-fabsf(x));
}

__global__ void __launch_bounds__(TPB)
k_main(const float* __restrict__ in, const float* __restrict__ tg,
       float* __restrict__ out) {
    __shared__ float sacc[8];
    __shared__ unsigned int s_last;
    if (threadIdx.x < 8) sacc[threadIdx.x] = 0.0f;

    if (blockIdx.x < NCONF) {
        // ============ CONF / NOOBJ BLOCK: 1024-cell window of one slice ============
        const int slice = blockIdx.x / BPS;
        const int pblk  = blockIdx.x % BPS;
        const int b = slice / NA;
        const int a = slice % NA;
        const int w0 = pblk * CPB;

        __shared__ unsigned int ssup32[CPB / 4];
        unsigned char* ssup = (unsigned char*)ssup32;
        if (threadIdx.x < CPB / 4) ssup32[threadIdx.x] = 0u;
        __syncthreads();

        if (threadIdx.x < NG) {
            const float* t = tg + (size_t)(b * NG + threadIdx.x) * 5;
            float gx = t[1] * ((float)NW / 416.0f);
            float gy = t[2] * ((float)NH / 416.0f);
            float gw = t[3] * ((float)NW / 416.0f);
            float gh = t[4] * ((float)NH / 416.0f);
            int gi = min(max((int)gx, 0), NW - 1);
            int gj = min(max((int)gy, 0), NH - 1);
            int cell = gj * NW + gi;
            if (cell >= w0 && cell < w0 + CPB) {
                float area_g = (gw + 1.0f) * (gh + 1.0f);
                float iw = fmaxf(fminf(gw, c_aw[a]) + 1.0f, 0.0f);
                float ih = fmaxf(fminf(gh, c_ah[a]) + 1.0f, 0.0f);
                float inter = iw * ih;
                float area_a = (c_aw[a] + 1.0f) * (c_ah[a] + 1.0f);
                float iou = inter / (area_g + area_a - inter + 1e-16f);
                if (iou > 0.5f) ssup[cell - w0] = 1;
            }
        }
        __syncthreads();

        // noobj: one float4 per thread; linear parts + ONE log of the u-product
        float snoobj = 0.f;
        const float* confc = in + (size_t)(b * 255 + a * ATTRS + 4) * HW;
        const int f = (w0 >> 2) + threadIdx.x;
        if (f < F4C) {
            float4 cv = reinterpret_cast<const float4*>(confc)[f];
            const int lb = threadIdx.x * 4;
            float lin = 0.0f, prod = 1.0f;
            if (!ssup[lb + 0]) { lin += fmaxf(cv.x, 0.0f); prod *= spu(cv.x); }
            if (!ssup[lb + 1]) { lin += fmaxf(cv.y, 0.0f); prod *= spu(cv.y); }
            if (!ssup[lb + 2]) { lin += fmaxf(cv.z, 0.0f); prod *= spu(cv.z); }
            if (!ssup[lb + 3]) { lin += fmaxf(cv.w, 0.0f); prod *= spu(cv.w); }
            snoobj = lin + __logf(prod);
        }
        unsigned lane = threadIdx.x & 31;
#pragma unroll
        for (int o = 16; o > 0; o >>= 1) snoobj += __shfl_down_sync(0xffffffffu, snoobj, o);
        if (lane == 0 && snoobj != 0.0f) atomicAdd(&sacc[5], snoobj);
    } else {
        // ============ WINNER BLOCK: 3 targets, exactly 1 gather load/thread ========
        const int wb  = blockIdx.x - NCONF;
        const int b   = wb / WB_PER_B;
        const int lo  = (wb % WB_PER_B) * TGT_PER_WB;

        __shared__ int    s_base[NG];
        __shared__ float4 s_box[NG];       // tx, ty, tw, th
        __shared__ int    s_cls[NG];
        __shared__ int    s_key[NG];
        __shared__ unsigned char s_alive[NG];

        if (threadIdx.x < NG) {
            const int t_i = threadIdx.x;
            const float* t = tg + (size_t)(b * NG + t_i) * 5;
            float gx = t[1] * ((float)NW / 416.0f);
            float gy = t[2] * ((float)NH / 416.0f);
            float gw = t[3] * ((float)NW / 416.0f);
            float gh = t[4] * ((float)NH / 416.0f);
            int gi = min(max((int)gx, 0), NW - 1);
            int gj = min(max((int)gy, 0), NH - 1);
            int cell = gj * NW + gi;
            float area_g = (gw + 1.0f) * (gh + 1.0f);
            float best_iou = -1.0f;
            int best = 0;
#pragma unroll
            for (int k = 0; k < 3; k++) {
                float iw = fmaxf(fminf(gw, c_aw[k]) + 1.0f, 0.0f);
                float ih = fmaxf(fminf(gh, c_ah[k]) + 1.0f, 0.0f);
                float inter = iw * ih;
                float area_k = (c_aw[k] + 1.0f) * (c_ah[k] + 1.0f);
                float iou = inter / (area_g + area_k - inter + 1e-16f);
                if (iou > best_iou) { best_iou = iou; best = k; }  // first-max = jnp.argmax
            }
            s_key[t_i]  = best * HW + cell;
            s_base[t_i] = (b * 255 + best * ATTRS) * HW + cell;
            s_box[t_i]  = make_float4(gx - (float)gi, gy - (float)gj,
                                      logf(gw / c_aw[best] + 1e-16f),
                                      logf(gh / c_ah[best] + 1e-16f));
            s_cls[t_i]  = min(max((int)t[0], 0), NC - 1);
        }
        __syncthreads();
        if (threadIdx.x < NG) {
            unsigned char alive = 1;
            int key = s_key[threadIdx.x];
            for (int t2 = threadIdx.x + 1; t2 < NG; t2++)
                if (s_key[t2] == key) alive = 0;   // later scatter overwrites = max-g
            s_alive[threadIdx.x] = alive;
        }
        __syncthreads();

        float ax = 0.f, ay = 0.f, aw2 = 0.f, ah2 = 0.f, ac = 0.f;
        float acls = 0.f, np = 0.f;
        if (threadIdx.x < TGT_PER_WB * ATTRS) {
            const int tl  = threadIdx.x / ATTRS;
            const int ch  = threadIdx.x % ATTRS;
            const int tgt = lo + tl;
            if (tgt < NG && s_alive[tgt]) {
                const float x = __ldg(in + (size_t)s_base[tgt] + (size_t)ch * HW);
                if (ch >= 5) {
                    float t = (ch - 5 == s_cls[tgt]) ? 1.0f : 0.0f;
                    acls = sp(x) - t * x;           // bce(sigm(x), t)
                } else if (ch == 0) {
                    ax = sp(x) - s_box[tgt].x * x;
                    np = 1.0f;
                } else if (ch == 1) {
                    ay = sp(x) - s_box[tgt].y * x;
                } else if (ch == 2) {
                    float d = x - s_box[tgt].z; aw2 = d * d;
                } else if (ch == 3) {
                    float d = x - s_box[tgt].w; ah2 = d * d;
                } else {
                    ac = sp(x) - x;                 // bce(conf, 1) = sp(-x)
                }
            }
        }
        float vals[7] = {ax, ay, aw2, ah2, ac, acls, np};
        const int map[7] = {0, 1, 2, 3, 4, 6, 7};
        unsigned lane = threadIdx.x & 31;
#pragma unroll
        for (int k = 0; k < 7; k++) {
            float v = vals[k];
#pragma unroll
            for (int o = 16; o > 0; o >>= 1) v += __shfl_down_sync(0xffffffffu, v, o);
            if (lane == 0 && v != 0.0f) atomicAdd(&sacc[map[k]], v);
        }
    }
    __syncthreads();

    // ---- 8 global float REDs per block, done-ticket, last block finalizes ----
    if (threadIdx.x < 8) {
        float v = sacc[threadIdx.x];
        if (v != 0.0f) atomicAdd(&g_acc[threadIdx.x], v);
    }
    if (threadIdx.x == 0) {
        __threadfence();
        unsigned int v = atomicAdd(&g_done, 1u);
        s_last = (v == (unsigned int)(GRID - 1)) ? 1u : 0u;
    }
    __syncthreads();
    if (s_last && threadIdx.x == 0) {
        const double N = (double)CELLS;
        double lx = (double)g_acc[0] / N;
        double ly = (double)g_acc[1] / N;
        double lw = (double)g_acc[2] / N;
        double lh = (double)g_acc[3] / N;
        double lconf = (double)g_acc[4] / N + 0.5 * ((double)g_acc[5] / N);
        double denom = (double)g_acc[7] * (double)NC;
        if (denom < 1.0) denom = 1.0;
        double lcls = (double)g_acc[6] / denom;
        out[0] = (float)(2.5 * (lx + ly) + 2.5 * (lw + lh) + lconf + lcls);
#pragma unroll
        for (int k = 0; k < 8; k++) g_acc[k] = 0.0f;   // restore pristine state
        g_done = 0u;
        __threadfence();
    }
}

extern "C" void kernel_launch(void* const* d_in, const int* in_sizes, int n_in,
                              void* d_out, int out_size) {
    const float* inp = (const float*)d_in[0];   // [32,255,52,52]
    const float* tgt = (const float*)d_in[1];   // [32,50,5]
    k_main<<<GRID, TPB>>>(inp, tgt, (float*)d_out);
}